// round 7
// baseline (speedup 1.0000x reference)
#include <cuda_runtime.h>

#define KK    15
#define PADK  7
#define TW    128
#define TH    64
#define TROWS (TH + 2 * PADK)   // 78
#define HH    512
#define WW    512
#define CH    3

typedef unsigned long long ull;

// packed fp32x2 ops (sm_100+/sm_103a)
__device__ __forceinline__ void fma2(ull& d, ull a, ull b) {
    asm("fma.rn.f32x2 %0, %1, %2, %0;" : "+l"(d) : "l"(a), "l"(b));
}
__device__ __forceinline__ ull add2(ull a, ull b) {
    ull r;
    asm("add.rn.f32x2 %0, %1, %2;" : "=l"(r) : "l"(a), "l"(b));
    return r;
}
__device__ __forceinline__ ull pack2(float lo, float hi) {
    ull r;
    asm("mov.b64 %0, {%1, %2};" : "=l"(r) : "f"(lo), "f"(hi));
    return r;
}

__global__ __launch_bounds__(256, 2)
void gauss_blur_kernel(const float* __restrict__ xin_all,
                       const float* __restrict__ sigma,
                       float* __restrict__ out_all)
{
    __shared__ __align__(16) float temp[TROWS][TW];   // 39936 B
    __shared__ float wsh[KK];

    const int bc = blockIdx.z;          // b * C + c
    const int b  = bc / CH;

    // --- per-batch separable weights: w_i = g_i / sqrt(S^2 + 1e-8) ---
    if (threadIdx.x == 0) {
        float s  = sigma[b];
        float s2 = 2.0f * s * s + 1e-8f;
        float g[KK];
        float S = 0.0f;
        #pragma unroll
        for (int i = 0; i < KK; i++) {
            float d = (float)(i - PADK);
            g[i] = expf(-(d * d) / s2);
            S += g[i];
        }
        float inv = rsqrtf(S * S + 1e-8f);
        #pragma unroll
        for (int i = 0; i < KK; i++) wsh[i] = g[i] * inv;
    }
    __syncthreads();

    float wl[KK];
    #pragma unroll
    for (int i = 0; i < KK; i++) wl[i] = wsh[i];

    const float* __restrict__ img    = xin_all + (size_t)bc * HH * WW;
    float*       __restrict__ outimg = out_all + (size_t)bc * HH * WW;
    const int y0 = blockIdx.y * TH;
    const int x0 = blockIdx.x * TW;

    // ---------------- Phase 1: horizontal conv into shared (R5 shape) ----------------
    // 16 x-groups of 8 outputs x 16 row-lanes. Aligned 24-float window via 6x float4.
    {
        const int xg   = threadIdx.x & 15;
        const int ry   = threadIdx.x >> 4;
        const int gx0a = x0 + xg * 8 - 8;        // 32B-aligned window start
        // taps for output j (j=0..7) are in[1 + j + k], k=0..14

        for (int r = ry; r < TROWS; r += 16) {
            const int gy = y0 - PADK + r;
            float in[24];
            if ((unsigned)gy < (unsigned)HH) {
                const float* row = img + (size_t)gy * WW;
                #pragma unroll
                for (int v = 0; v < 6; v++) {
                    const int gxv = gx0a + v * 4;
                    if ((unsigned)gxv <= (unsigned)(WW - 4)) {
                        float4 t = *reinterpret_cast<const float4*>(row + gxv);
                        in[v * 4 + 0] = t.x; in[v * 4 + 1] = t.y;
                        in[v * 4 + 2] = t.z; in[v * 4 + 3] = t.w;
                    } else {
                        #pragma unroll
                        for (int e = 0; e < 4; e++) {
                            int gx = gxv + e;
                            in[v * 4 + e] = ((unsigned)gx < (unsigned)WW) ? row[gx] : 0.0f;
                        }
                    }
                }
            } else {
                #pragma unroll
                for (int i = 0; i < 24; i++) in[i] = 0.0f;
            }

            float acc[8];
            #pragma unroll
            for (int j = 0; j < 8; j++) {
                float a = 0.0f;
                #pragma unroll
                for (int k = 0; k < KK; k++)
                    a = fmaf(wl[k], in[1 + j + k], a);
                acc[j] = a;
            }

            float4* dst = reinterpret_cast<float4*>(&temp[r][xg * 8]);
            dst[0] = make_float4(acc[0], acc[1], acc[2], acc[3]);
            dst[1] = make_float4(acc[4], acc[5], acc[6], acc[7]);
        }
    }
    __syncthreads();

    // ---------------- Phase 2: vertical conv, packed f32x2 + symmetric weights ----------
    // 64 column-pairs x 4 vertical quarters of 16 rows. Gaussian symmetry w[k]==w[14-k]
    // -> only 8 packed weight regs; each packed op produces 2 columns.
    {
        const int cp    = threadIdx.x & 63;      // column pair: cols 2cp, 2cp+1
        const int q     = threadIdx.x >> 6;      // 0..3
        const int ybase = q * 16;

        ull w2[8];
        #pragma unroll
        for (int k = 0; k < 8; k++) w2[k] = pack2(wl[k], wl[k]);

        ull win[KK];                              // ring, constant-indexed after unroll
        #pragma unroll
        for (int i = 0; i < KK; i++)
            win[i] = *reinterpret_cast<const ull*>(&temp[ybase + i][cp * 2]);

        float* obase = outimg + (size_t)(y0 + ybase) * WW + x0 + cp * 2;

        #pragma unroll
        for (int j = 0; j < 16; j++) {
            ull acc = 0ULL;                       // (0.0f, 0.0f)
            #pragma unroll
            for (int k = 0; k < 7; k++) {
                ull t = add2(win[(j + k) % KK], win[(j + 14 - k) % KK]);
                fma2(acc, w2[k], t);
            }
            fma2(acc, w2[7], win[(j + 7) % KK]);
            *reinterpret_cast<ull*>(obase + (size_t)j * WW) = acc;
            if (j < 15)
                win[j % KK] = *reinterpret_cast<const ull*>(&temp[ybase + j + KK][cp * 2]);
        }
    }
}

extern "C" void kernel_launch(void* const* d_in, const int* in_sizes, int n_in,
                              void* d_out, int out_size)
{
    const float* x     = (const float*)d_in[0];
    const float* sigma = (const float*)d_in[1];
    float*       out   = (float*)d_out;

    const int B = in_sizes[1];                 // sigma has one entry per batch
    dim3 grid(WW / TW, HH / TH, B * CH);       // (4, 8, 96)
    gauss_blur_kernel<<<grid, 256>>>(x, sigma, out);
}

// round 8
// speedup vs baseline: 1.3311x; 1.3311x over previous
#include <cuda_runtime.h>

#define KK    15
#define PADK  7
#define TW    128
#define TH    64
#define TROWS (TH + 2 * PADK)   // 78
#define HH    512
#define WW    512
#define CH    3

typedef unsigned long long ull;

// packed fp32x2 ops (sm_100+/sm_103a)
__device__ __forceinline__ void fma2(ull& d, ull a, ull b) {
    asm("fma.rn.f32x2 %0, %1, %2, %0;" : "+l"(d) : "l"(a), "l"(b));
}
__device__ __forceinline__ ull add2(ull a, ull b) {
    ull r;
    asm("add.rn.f32x2 %0, %1, %2;" : "=l"(r) : "l"(a), "l"(b));
    return r;
}
__device__ __forceinline__ ull bcast2(float v) {
    ull r;
    asm("mov.b64 %0, {%1, %1};" : "=l"(r) : "f"(v));
    return r;
}

__global__ __launch_bounds__(256, 4)   // hard cap 64 regs -> 4 blocks/SM
void gauss_blur_kernel(const float* __restrict__ xin_all,
                       const float* __restrict__ sigma,
                       float* __restrict__ out_all)
{
    __shared__ __align__(16) float temp[TROWS][TW];   // 39936 B
    __shared__ float wsh[KK];

    const int bc = blockIdx.z;          // b * C + c
    const int b  = bc / CH;

    // --- per-batch separable weights: w_i = g_i / sqrt(S^2 + 1e-8) ---
    if (threadIdx.x == 0) {
        float s  = sigma[b];
        float s2 = 2.0f * s * s + 1e-8f;
        float g[KK];
        float S = 0.0f;
        #pragma unroll
        for (int i = 0; i < KK; i++) {
            float d = (float)(i - PADK);
            g[i] = expf(-(d * d) / s2);
            S += g[i];
        }
        float inv = rsqrtf(S * S + 1e-8f);
        #pragma unroll
        for (int i = 0; i < KK; i++) wsh[i] = g[i] * inv;
    }
    __syncthreads();

    float wl[KK];
    #pragma unroll
    for (int i = 0; i < KK; i++) wl[i] = wsh[i];

    const float* __restrict__ img    = xin_all + (size_t)bc * HH * WW;
    float*       __restrict__ outimg = out_all + (size_t)bc * HH * WW;
    const int y0 = blockIdx.y * TH;
    const int x0 = blockIdx.x * TW;

    // ---------------- Phase 1: horizontal conv into shared (R5 shape) ----------------
    // 16 x-groups of 8 outputs x 16 row-lanes. Aligned 24-float window via 6x float4.
    {
        const int xg   = threadIdx.x & 15;
        const int ry   = threadIdx.x >> 4;
        const int gx0a = x0 + xg * 8 - 8;        // 32B-aligned window start

        for (int r = ry; r < TROWS; r += 16) {
            const int gy = y0 - PADK + r;
            float in[24];
            if ((unsigned)gy < (unsigned)HH) {
                const float* row = img + (size_t)gy * WW;
                #pragma unroll
                for (int v = 0; v < 6; v++) {
                    const int gxv = gx0a + v * 4;
                    if ((unsigned)gxv <= (unsigned)(WW - 4)) {
                        float4 t = *reinterpret_cast<const float4*>(row + gxv);
                        in[v * 4 + 0] = t.x; in[v * 4 + 1] = t.y;
                        in[v * 4 + 2] = t.z; in[v * 4 + 3] = t.w;
                    } else {
                        #pragma unroll
                        for (int e = 0; e < 4; e++) {
                            int gx = gxv + e;
                            in[v * 4 + e] = ((unsigned)gx < (unsigned)WW) ? row[gx] : 0.0f;
                        }
                    }
                }
            } else {
                #pragma unroll
                for (int i = 0; i < 24; i++) in[i] = 0.0f;
            }

            float acc[8];
            #pragma unroll
            for (int j = 0; j < 8; j++) {
                float a = 0.0f;
                #pragma unroll
                for (int k = 0; k < KK; k++)
                    a = fmaf(wl[k], in[1 + j + k], a);
                acc[j] = a;
            }

            float4* dst = reinterpret_cast<float4*>(&temp[r][xg * 8]);
            dst[0] = make_float4(acc[0], acc[1], acc[2], acc[3]);
            dst[1] = make_float4(acc[4], acc[5], acc[6], acc[7]);
        }
    }
    __syncthreads();

    // ---------------- Phase 2: vertical conv, packed f32x2 + symmetric weights ----------
    // 64 column-pairs x 4 vertical quarters of 16 rows. Gaussian symmetry w[k]==w[14-k]:
    // 7 add2 + 8 fma2 per 2-column output pair. Weights packed on the fly (ALU movs).
    {
        const int cp    = threadIdx.x & 63;      // column pair: cols 2cp, 2cp+1
        const int q     = threadIdx.x >> 6;      // 0..3
        const int ybase = q * 16;

        ull win[KK];                              // ring, constant-indexed after unroll
        #pragma unroll
        for (int i = 0; i < KK; i++)
            win[i] = *reinterpret_cast<const ull*>(&temp[ybase + i][cp * 2]);

        float* obase = outimg + (size_t)(y0 + ybase) * WW + x0 + cp * 2;

        #pragma unroll
        for (int j = 0; j < 16; j++) {
            ull acc = 0ULL;                       // (0.0f, 0.0f)
            #pragma unroll
            for (int k = 0; k < 7; k++) {
                ull t = add2(win[(j + k) % KK], win[(j + 14 - k) % KK]);
                fma2(acc, bcast2(wl[k]), t);
            }
            fma2(acc, bcast2(wl[7]), win[(j + 7) % KK]);
            *reinterpret_cast<ull*>(obase + (size_t)j * WW) = acc;
            if (j < 15)
                win[j % KK] = *reinterpret_cast<const ull*>(&temp[ybase + j + KK][cp * 2]);
        }
    }
}

extern "C" void kernel_launch(void* const* d_in, const int* in_sizes, int n_in,
                              void* d_out, int out_size)
{
    const float* x     = (const float*)d_in[0];
    const float* sigma = (const float*)d_in[1];
    float*       out   = (float*)d_out;

    const int B = in_sizes[1];                 // sigma has one entry per batch
    dim3 grid(WW / TW, HH / TH, B * CH);       // (4, 8, 96)
    gauss_blur_kernel<<<grid, 256>>>(x, sigma, out);
}